// round 1
// baseline (speedup 1.0000x reference)
#include <cuda_runtime.h>
#include <math.h>

#define B_    4
#define T_    1000
#define C_    1024
#define H_    16
#define D_    64
#define M_TOK (B_*T_)   // 4000

// Scratch (allocation-free: device globals)
__device__ float g_q[B_*H_*T_*D_];
__device__ float g_k[B_*H_*T_*D_];
__device__ float g_v[B_*H_*T_*D_];
__device__ float g_y[M_TOK*C_];
__device__ float g_cos[T_*(D_/2)];
__device__ float g_sin[T_*(D_/2)];

// ---------------------------------------------------------------------------
// RoPE cos/sin table: matches reference fp32 math (theta fp32, ang = t*theta fp32)
// ---------------------------------------------------------------------------
__global__ void rope_table_kernel() {
    int t = blockIdx.x;      // 0..T-1
    int i = threadIdx.x;     // 0..31  (pair index, d = 2*i)
    float theta = (float)pow(10000.0, -(double)(2 * i) / 64.0);
    float ang = (float)t * theta;
    g_cos[t * 32 + i] = cosf(ang);
    g_sin[t * 32 + i] = sinf(ang);
}

// ---------------------------------------------------------------------------
// 128x128x8 fp32 SGEMM, 256 threads, 8x8 per thread.
// MODE 0: C = x @ W_attn, epilogue scatters Q/K/V to [B,H,T,D] with fused RoPE.
// MODE 1: C = g_y @ W_proj, plain row-major write to Cout.
// ---------------------------------------------------------------------------
template<int MODE>
__global__ void __launch_bounds__(256)
gemm128(const float* __restrict__ Ain, const float* __restrict__ Bw,
        float* __restrict__ Cout, int M, int N, int K)
{
    const float* A = (MODE == 1) ? (const float*)g_y : Ain;

    __shared__ float As[8][128];   // transposed A tile
    __shared__ float Bs[8][128];

    int tid = threadIdx.x;
    int bm = blockIdx.y * 128;
    int bn = blockIdx.x * 128;
    int ty = tid >> 4;        // 0..15
    int tx = tid & 15;        // 0..15

    float acc[8][8];
#pragma unroll
    for (int i = 0; i < 8; i++)
#pragma unroll
        for (int j = 0; j < 8; j++) acc[i][j] = 0.f;

    int arow  = tid >> 1;          // 0..127
    int acol4 = (tid & 1) * 4;     // 0 or 4
    int brow  = tid >> 5;          // 0..7
    int bcol  = (tid & 31) * 4;    // 0..124

    for (int k0 = 0; k0 < K; k0 += 8) {
        float4 av = make_float4(0.f, 0.f, 0.f, 0.f);
        if (bm + arow < M)
            av = *(const float4*)(A + (size_t)(bm + arow) * K + k0 + acol4);
        As[acol4 + 0][arow] = av.x;
        As[acol4 + 1][arow] = av.y;
        As[acol4 + 2][arow] = av.z;
        As[acol4 + 3][arow] = av.w;

        *(float4*)&Bs[brow][bcol] =
            *(const float4*)(Bw + (size_t)(k0 + brow) * N + bn + bcol);

        __syncthreads();

#pragma unroll
        for (int kk = 0; kk < 8; kk++) {
            float ra[8], rb[8];
#pragma unroll
            for (int i = 0; i < 8; i++) ra[i] = As[kk][ty * 8 + i];
#pragma unroll
            for (int j = 0; j < 8; j++) rb[j] = Bs[kk][tx * 8 + j];
#pragma unroll
            for (int i = 0; i < 8; i++)
#pragma unroll
                for (int j = 0; j < 8; j++)
                    acc[i][j] = fmaf(ra[i], rb[j], acc[i][j]);
        }
        __syncthreads();
    }

    if (MODE == 1) {
#pragma unroll
        for (int i = 0; i < 8; i++) {
            int gr = bm + ty * 8 + i;
            if (gr >= M) continue;
            float* dst = Cout + (size_t)gr * N + bn + tx * 8;
            *(float4*)dst       = make_float4(acc[i][0], acc[i][1], acc[i][2], acc[i][3]);
            *(float4*)(dst + 4) = make_float4(acc[i][4], acc[i][5], acc[i][6], acc[i][7]);
        }
    } else {
        // 8 consecutive columns live inside a single head (64-aligned groups)
        int c0    = bn + tx * 8;
        int which = c0 >> 10;            // 0=Q, 1=K, 2=V
        int h     = (c0 & 1023) >> 6;
        int dbase = c0 & 63;
#pragma unroll
        for (int i = 0; i < 8; i++) {
            int gr = bm + ty * 8 + i;
            if (gr >= M) continue;
            int b = gr / T_;
            int t = gr - b * T_;
            size_t base = ((size_t)(b * H_ + h) * T_ + t) * D_ + dbase;
            if (which == 2) {
                *(float4*)&g_v[base]     = make_float4(acc[i][0], acc[i][1], acc[i][2], acc[i][3]);
                *(float4*)&g_v[base + 4] = make_float4(acc[i][4], acc[i][5], acc[i][6], acc[i][7]);
            } else {
                float* dst = (which == 0 ? g_q : g_k) + base;
#pragma unroll
                for (int p = 0; p < 4; p++) {
                    int pi = (dbase >> 1) + p;
                    float ct = g_cos[t * 32 + pi];
                    float st = g_sin[t * 32 + pi];
                    float x0 = acc[i][2 * p], x1 = acc[i][2 * p + 1];
                    dst[2 * p]     = x0 * ct - x1 * st;
                    dst[2 * p + 1] = x1 * ct + x0 * st;
                }
            }
        }
    }
}

// ---------------------------------------------------------------------------
// Flash-style causal attention.
// Grid: (qtiles=16, H, B), 64 threads; each thread owns one q row.
// K/V streamed in 32-row tiles; online softmax; score tile in smem (j-major).
// ---------------------------------------------------------------------------
__global__ void __launch_bounds__(64) attn_kernel() {
    int qt = gridDim.x - 1 - blockIdx.x;   // heavy tiles scheduled first
    int h  = blockIdx.y;
    int b  = blockIdx.z;
    int r  = threadIdx.x;                  // q row within tile
    int qrow = qt * 64 + r;
    bool active = (qrow < T_);

    __shared__ float Ks[32][64];
    __shared__ float Vs[32][64];
    __shared__ float Sb[32][64];           // [k-col][q-row] — conflict-free

    const float scale = 0.125f;            // 1/sqrt(64)

    float q[64], o[64];
#pragma unroll
    for (int d = 0; d < 64; d++) o[d] = 0.f;

    {
        size_t qoff = ((size_t)(b * H_ + h) * T_ + (active ? qrow : 0)) * D_;
#pragma unroll
        for (int d = 0; d < 64; d += 4) {
            float4 v = *(const float4*)&g_q[qoff + d];
            q[d]     = v.x * scale;
            q[d + 1] = v.y * scale;
            q[d + 2] = v.z * scale;
            q[d + 3] = v.w * scale;
        }
    }

    float m = -1e30f, l = 0.f;
    int maxq = min(qt * 64 + 63, T_ - 1);
    int nkt  = maxq / 32 + 1;
    size_t kvbase = (size_t)(b * H_ + h) * T_ * D_;

    for (int kt = 0; kt < nkt; kt++) {
        int kbase = kt * 32;

        // cooperative load: 2048 floats each for K and V, fully coalesced
#pragma unroll
        for (int u = 0; u < 8; u++) {
            int e4 = u * 64 + r;            // float4 index 0..511
            int j  = e4 >> 4;               // k row within tile
            int d  = (e4 & 15) * 4;
            int kg = kbase + j;
            float4 kv = make_float4(0.f, 0.f, 0.f, 0.f);
            float4 vv = make_float4(0.f, 0.f, 0.f, 0.f);
            if (kg < T_) {
                kv = *(const float4*)&g_k[kvbase + (size_t)kg * D_ + d];
                vv = *(const float4*)&g_v[kvbase + (size_t)kg * D_ + d];
            }
            *(float4*)&Ks[j][d] = kv;
            *(float4*)&Vs[j][d] = vv;
        }
        __syncthreads();

        if (active) {
            // pass 1: scores + tile max (4 independent accumulator chains)
            float tmax = -1e30f;
#pragma unroll 1
            for (int j0 = 0; j0 < 32; j0 += 4) {
                float s0 = 0.f, s1 = 0.f, s2 = 0.f, s3 = 0.f;
#pragma unroll
                for (int d = 0; d < 64; d++) {
                    float qd = q[d];
                    s0 = fmaf(qd, Ks[j0 + 0][d], s0);
                    s1 = fmaf(qd, Ks[j0 + 1][d], s1);
                    s2 = fmaf(qd, Ks[j0 + 2][d], s2);
                    s3 = fmaf(qd, Ks[j0 + 3][d], s3);
                }
                if (kbase + j0 + 0 > qrow || kbase + j0 + 0 >= T_) s0 = -1e30f;
                if (kbase + j0 + 1 > qrow || kbase + j0 + 1 >= T_) s1 = -1e30f;
                if (kbase + j0 + 2 > qrow || kbase + j0 + 2 >= T_) s2 = -1e30f;
                if (kbase + j0 + 3 > qrow || kbase + j0 + 3 >= T_) s3 = -1e30f;
                Sb[j0 + 0][r] = s0;
                Sb[j0 + 1][r] = s1;
                Sb[j0 + 2][r] = s2;
                Sb[j0 + 3][r] = s3;
                tmax = fmaxf(tmax, fmaxf(fmaxf(s0, s1), fmaxf(s2, s3)));
            }

            // online softmax rescale (once per tile)
            float mnew = fmaxf(m, tmax);
            float f = __expf(m - mnew);
            l *= f;
#pragma unroll
            for (int d = 0; d < 64; d++) o[d] *= f;

            // pass 2: probs + O accumulation
#pragma unroll 1
            for (int j = 0; j < 32; j++) {
                float p = __expf(Sb[j][r] - mnew);
                l += p;
#pragma unroll
                for (int d = 0; d < 64; d++)
                    o[d] = fmaf(p, Vs[j][d], o[d]);
            }
            m = mnew;
        }
        __syncthreads();
    }

    if (active) {
        float inv = 1.f / l;
        float* yp = &g_y[((size_t)(b * T_) + qrow) * C_ + h * D_];
#pragma unroll
        for (int d = 0; d < 64; d += 4) {
            *(float4*)&yp[d] = make_float4(o[d] * inv, o[d + 1] * inv,
                                           o[d + 2] * inv, o[d + 3] * inv);
        }
    }
}

// ---------------------------------------------------------------------------
// Launch: rope table -> QKV GEMM (+RoPE scatter) -> attention -> proj GEMM
// Inputs (metadata order): x[f32], attn_mask[bool, ignored: it's tril],
//                          W_attn[f32 1024x3072], W_proj[f32 1024x1024]
// ---------------------------------------------------------------------------
extern "C" void kernel_launch(void* const* d_in, const int* in_sizes, int n_in,
                              void* d_out, int out_size)
{
    const float* x      = (const float*)d_in[0];
    const float* W_attn = (const float*)d_in[2];
    const float* W_proj = (const float*)d_in[3];
    float* out = (float*)d_out;

    rope_table_kernel<<<T_, 32>>>();

    dim3 g_qkv(3072 / 128, (M_TOK + 127) / 128);   // 24 x 32
    gemm128<0><<<g_qkv, 256>>>(x, W_attn, nullptr, M_TOK, 3072, 1024);

    dim3 g_attn((T_ + 63) / 64, H_, B_);           // 16 x 16 x 4
    attn_kernel<<<g_attn, 64>>>();

    dim3 g_proj(1024 / 128, (M_TOK + 127) / 128);  // 8 x 32
    gemm128<1><<<g_proj, 256>>>(nullptr, W_proj, out, M_TOK, 1024, 1024);
}